// round 12
// baseline (speedup 1.0000x reference)
#include <cuda_runtime.h>

#define B_   4096
#define T_   64
#define OBS_ 64
#define H_   64
#define A_   8
#define S_   201
#define G_   16
#define NTHR 256

typedef unsigned long long u64;
typedef unsigned int u32;

// ---- packed f32x2 helpers (sm_100+ PTX) ----
__device__ __forceinline__ u64 fma2(u64 a, u64 b, u64 c) {
    u64 d;
    asm("fma.rn.f32x2 %0, %1, %2, %3;" : "=l"(d) : "l"(a), "l"(b), "l"(c));
    return d;
}
__device__ __forceinline__ u64 pack2(float x, float y) {
    u64 d;
    asm("mov.b64 %0, {%1, %2};" : "=l"(d) : "r"(__float_as_uint(x)), "r"(__float_as_uint(y)));
    return d;
}
__device__ __forceinline__ float2 unpack2(u64 a) {
    u32 lo, hi;
    asm("mov.b64 {%0, %1}, %2;" : "=r"(lo), "=r"(hi) : "l"(a));
    float2 r; r.x = __uint_as_float(lo); r.y = __uint_as_float(hi);
    return r;
}

// XLA/Eigen f32 fast-tanh clone — decision-critical, validated since R3. DO NOT TOUCH.
__device__ __forceinline__ float tanh_xla(float x) {
    float xc = fminf(fmaxf(x, -7.90531110763549805f), 7.90531110763549805f);
    float x2 = xc * xc;
    float p = -2.76076847742355e-16f;
    p = __fmaf_rn(p, x2, 2.00018790482477e-13f);
    p = __fmaf_rn(p, x2, -8.60467152213735e-11f);
    p = __fmaf_rn(p, x2, 5.12229709037114e-08f);
    p = __fmaf_rn(p, x2, 1.48572235717979e-05f);
    p = __fmaf_rn(p, x2, 6.37261928875436e-04f);
    p = __fmaf_rn(p, x2, 4.89352455891786e-03f);
    float num = xc * p;
    float q = 1.19825839466702e-06f;
    q = __fmaf_rn(q, x2, 1.18534705686654e-04f);
    q = __fmaf_rn(q, x2, 2.26843463243900e-03f);
    q = __fmaf_rn(q, x2, 4.89352518554385e-03f);
    float r = __fdiv_rn(num, q);
    return (fabsf(x) < 0.0004f) ? x : r;
}

// output layout (flattened tuple, float32)
#define OFF_VAL ((size_t)B_ * T_ * A_)
#define OFF_STK (OFF_VAL + (size_t)T_ * B_)
#define OFF_PTR (OFF_STK + (size_t)B_ * S_ * H_)

// shared memory layout (floats) — R3/R11 layout
#define SM_W1T   0                       // 128*64
#define SM_W2T   (SM_W1T + 8192)         // 64*64
#define SM_WHT   (SM_W2T + 4096)         // 64*12
#define SM_B1    (SM_WHT + 768)          // 64
#define SM_B2    (SM_B1 + 64)            // 64
#define SM_BH    (SM_B2 + 64)            // 12
#define SM_IN    (SM_BH + 12)            // 128*18
#define SM_HT    (SM_IN + 2304)          // 64*18
#define SM_PT    (SM_HT + 1152)          // 64*18
#define SM_LS    (SM_PT + 1152)          // 16*4
#define SM_INTS  (SM_LS + 64)            // ptrS(16) ptrOld(16) opS(16) wbits(112)
#define SMEM_BYTES ((SM_INTS + 160) * 4)

__global__ void __launch_bounds__(NTHR, 2) stacknet_kernel(
    const float* __restrict__ x,        const float* __restrict__ stack_in,
    const int*   __restrict__ ptr_in,
    const float* __restrict__ W1,  const float* __restrict__ b1,
    const float* __restrict__ W2,  const float* __restrict__ b2,
    const float* __restrict__ Ws,  const float* __restrict__ bsv,
    const float* __restrict__ Wp,  const float* __restrict__ bp,
    const float* __restrict__ Wv,  const float* __restrict__ bv,
    float* __restrict__ out)
{
    extern __shared__ float sm[];
    float* W1t  = sm + SM_W1T;
    float* W2t  = sm + SM_W2T;
    float* Wht  = sm + SM_WHT;
    float* b1s  = sm + SM_B1;
    float* b2s  = sm + SM_B2;
    float* bhs  = sm + SM_BH;
    float* InT  = sm + SM_IN;     // [128][18]  concat(x_t, top) transposed
    float* Ht   = sm + SM_HT;     // [64][18]
    float* Pt   = sm + SM_PT;     // [64][18]
    float* Ls   = sm + SM_LS;     // [16][4]
    int*   ptrS    = (int*)(sm + SM_INTS);
    int*   ptrOldS = ptrS + 16;
    int*   opS     = ptrOldS + 16;
    u32*   wbits   = (u32*)(opS + 16);   // [16][7]

    const int tid  = threadIdx.x;
    const int base = blockIdx.x * G_;

    // ---- load weights (transposed for conflict-free vector LDS) ----
    for (int i = tid; i < 8192; i += NTHR) { int j = i >> 7, k = i & 127; W1t[k * 64 + j] = W1[i]; }
    for (int i = tid; i < 4096; i += NTHR) { int j = i >> 6, k = i & 63;  W2t[k * 64 + j] = W2[i]; }
    for (int i = tid; i < 192;  i += NTHR) { int h = i >> 6, k = i & 63;  Wht[k * 12 + h] = Ws[i]; }
    for (int i = tid; i < 512;  i += NTHR) { int h = 3 + (i >> 6), k = i & 63; Wht[k * 12 + h] = Wp[i]; }
    for (int i = tid; i < 64;   i += NTHR) { Wht[i * 12 + 11] = Wv[i]; }
    if (tid < 64) { b1s[tid] = b1[tid]; b2s[tid] = b2[tid]; }
    if (tid < 3)               bhs[tid] = bsv[tid];
    if (tid >= 3 && tid < 11)  bhs[tid] = bp[tid - 3];
    if (tid == 11)             bhs[11]  = bv[0];
    for (int i = tid; i < G_ * 7; i += NTHR) wbits[i] = 0;
    if (tid < G_) ptrS[tid] = ptr_in[base + tid];
    __syncthreads();

    // matmul map: 1 elem x 4 cols per thread
    const int e9 = tid & 15;        // element (matmul row)
    const int c4 = tid >> 4;        // col quad: cols 4*c4..4*c4+3
    // IO map: element e, 4-float segment seg
    const int e   = tid >> 4;
    const int seg = tid & 15;       // features seg*4..seg*4+3

    const size_t xrow = (size_t)(base + e) * T_ * OBS_;
    const size_t srow = (size_t)(base + e) * S_;
    float* ostk = out + OFF_STK;

    // ---- initial prefetch: x_0 and top = stack_in[b][ptr0] ----
    float4 xr, cr;
    {
        xr = *(const float4*)(x + xrow + seg * 4);
        int p0 = ptrS[e];
        cr = *(const float4*)(stack_in + (srow + p0) * H_ + seg * 4);
    }

    for (int t = 0; t < T_; ++t) {
        // scatter x_t and top into InT (transposed, stride 18)
        {
            const float* xf = (const float*)&xr;
            const float* cf = (const float*)&cr;
            #pragma unroll
            for (int i = 0; i < 4; ++i) {
                InT[(seg * 4 + i) * 18 + e]      = xf[i];
                InT[(64 + seg * 4 + i) * 18 + e] = cf[i];
            }
        }
        __syncthreads();

        // prefetch x_{t+1} (hidden under W1 compute)
        if (t + 1 < T_) {
            xr = *(const float4*)(x + xrow + (size_t)(t + 1) * OBS_ + seg * 4);
        }

        // ---- W1: [16 x 128] @ [128 x 64], 1x4 tile ----
        u64 a0 = 0ull, a1 = 0ull;
        {
            const float* inb = &InT[e9];
            const float* wb  = &W1t[4 * c4];
            #pragma unroll 8
            for (int k = 0; k < 128; ++k) {
                float in = inb[k * 18];
                ulonglong2 wv = *(const ulonglong2*)(wb + k * 64);
                u64 ax = pack2(in, in);
                a0 = fma2(ax, wv.x, a0);
                a1 = fma2(ax, wv.y, a1);
            }
        }
        {
            float2 v0 = unpack2(a0), v1 = unpack2(a1);
            int j0 = 4 * c4;
            Ht[j0 * 18 + e9]       = tanh_xla(v0.x + b1s[j0]);
            Ht[(j0 + 1) * 18 + e9] = tanh_xla(v0.y + b1s[j0 + 1]);
            Ht[(j0 + 2) * 18 + e9] = tanh_xla(v1.x + b1s[j0 + 2]);
            Ht[(j0 + 3) * 18 + e9] = tanh_xla(v1.y + b1s[j0 + 3]);
        }
        __syncthreads();

        // ---- W2: [16 x 64] @ [64 x 64], 1x4 tile ----
        a0 = 0ull; a1 = 0ull;
        {
            const float* inb = &Ht[e9];
            const float* wb  = &W2t[4 * c4];
            #pragma unroll 8
            for (int k = 0; k < 64; ++k) {
                float in = inb[k * 18];
                ulonglong2 wv = *(const ulonglong2*)(wb + k * 64);
                u64 ax = pack2(in, in);
                a0 = fma2(ax, wv.x, a0);
                a1 = fma2(ax, wv.y, a1);
            }
        }
        {
            float2 v0 = unpack2(a0), v1 = unpack2(a1);
            int j0 = 4 * c4;
            Pt[j0 * 18 + e9]       = tanh_xla(v0.x + b2s[j0]);
            Pt[(j0 + 1) * 18 + e9] = tanh_xla(v0.y + b2s[j0 + 1]);
            Pt[(j0 + 2) * 18 + e9] = tanh_xla(v1.x + b2s[j0 + 2]);
            Pt[(j0 + 3) * 18 + e9] = tanh_xla(v1.y + b2s[j0 + 3]);
        }
        __syncthreads();

        // ---- heads: 192 dots of length 64, single pass, bias LAST (R3 order) ----
        if (tid < 192) {
            int ee = tid / 12, h = tid - 12 * ee;
            float acc = 0.0f;
            #pragma unroll 8
            for (int k = 0; k < 64; ++k) acc = __fmaf_rn(Pt[k * 18 + ee], Wht[k * 12 + h], acc);
            acc += bhs[h];
            if (h < 3)       Ls[ee * 4 + h] = acc;
            else if (h < 11) out[((size_t)(base + ee) * T_ + t) * A_ + (h - 3)] = acc;
            else             out[OFF_VAL + (size_t)t * B_ + (base + ee)] = acc;
        }
        __syncthreads();

        // ---- argmax + pointer update (one thread per element) ----
        if (tid < G_) {
            int ee = tid;
            float l0 = Ls[ee * 4], l1 = Ls[ee * 4 + 1], l2 = Ls[ee * 4 + 2];
            int op = 0; float bst = l0;
            if (l1 > bst) { bst = l1; op = 1; }
            if (l2 > bst) { op = 2; }
            int p = ptrS[ee];
            ptrOldS[ee] = p; opS[ee] = op;
            int np = p + op - 1; np = np < 0 ? 0 : np;
            ptrS[ee] = np;
            if (op == 2) wbits[ee * 7 + (p >> 5)] |= (1u << (p & 31));
        }
        __syncthreads();

        // ---- push write-through (gather from Pt) + next-top reload ----
        {
            if (opS[e] == 2) {
                float pv[4];
                #pragma unroll
                for (int i = 0; i < 4; ++i) pv[i] = Pt[(seg * 4 + i) * 18 + e];
                *(float4*)(ostk + (srow + ptrOldS[e]) * H_ + seg * 4)
                    = make_float4(pv[0], pv[1], pv[2], pv[3]);
            }
            if (t + 1 < T_) {
                int row = ptrS[e];
                bool written = (wbits[e * 7 + (row >> 5)] >> (row & 31)) & 1u;
                const float* sbase = written ? ostk : stack_in;
                cr = *(const float4*)(sbase + (srow + row) * H_ + seg * 4);
            }
        }
    }

    // final pointers (argmax writer thread == reader thread)
    if (tid < G_) out[OFF_PTR + base + tid] = (float)ptrS[tid];
    __syncthreads();

    // epilogue: copy never-written stack rows from input
    for (int it = tid; it < G_ * S_; it += NTHR) {
        int ee = it / S_, rr = it - S_ * ee;
        if (!((wbits[ee * 7 + (rr >> 5)] >> (rr & 31)) & 1u)) {
            const float4* src = (const float4*)(stack_in + ((size_t)(base + ee) * S_ + rr) * H_);
            float4* dst = (float4*)(out + OFF_STK + ((size_t)(base + ee) * S_ + rr) * H_);
            #pragma unroll
            for (int q = 0; q < 16; ++q) dst[q] = src[q];
        }
    }
}

extern "C" void kernel_launch(void* const* d_in, const int* in_sizes, int n_in,
                              void* d_out, int out_size) {
    (void)in_sizes; (void)n_in; (void)out_size;
    cudaFuncSetAttribute(stacknet_kernel, cudaFuncAttributeMaxDynamicSharedMemorySize, SMEM_BYTES);
    const float* x        = (const float*)d_in[0];
    const float* stack_in = (const float*)d_in[1];
    const int*   ptrs     = (const int*)  d_in[2];
    const float* W1 = (const float*)d_in[3];  const float* b1 = (const float*)d_in[4];
    const float* W2 = (const float*)d_in[5];  const float* b2 = (const float*)d_in[6];
    const float* Ws = (const float*)d_in[7];  const float* bs = (const float*)d_in[8];
    const float* Wp = (const float*)d_in[9];  const float* bp = (const float*)d_in[10];
    const float* Wv = (const float*)d_in[11]; const float* bv = (const float*)d_in[12];
    stacknet_kernel<<<B_ / G_, NTHR, SMEM_BYTES>>>(
        x, stack_in, ptrs, W1, b1, W2, b2, Ws, bs, Wp, bp, Wv, bv, (float*)d_out);
}